// round 17
// baseline (speedup 1.0000x reference)
#include <cuda_runtime.h>
#include <cuda_bf16.h>
#include <cstdint>
#include <math.h>

// Problem constants: B=32, S=64, E=256, H=4, D=64
#define NROWS 2048
#define EDIM  256
#define NQKV  768
#define NH    4
#define NCTA  128

// ---------------- scratch (__device__ globals, no allocs) -------------------
__device__ __nv_bfloat16 g_Bhi[NQKV * EDIM],  g_Blo[NQKV * EDIM];    // exp(Wqkv) [n][k]
__device__ __nv_bfloat16 g_Chi[EDIM * EDIM],  g_Clo[EDIM * EDIM];    // exp(Wo)   [n][k]
__device__ __nv_bfloat16 g_EOhi[NROWS * EDIM], g_EOlo[NROWS * EDIM]; // exp(attn out)
__device__ unsigned g_barctr = 0;        // full grid barrier (monotonic)
__device__ unsigned g_bctr[32] = {};     // per-b 4-CTA barriers (monotonic)

// ---------------- helpers (base ISA only — sm_103 non-variant) --------------
__device__ __forceinline__ uint32_t smem_u32(const void* p) {
    uint32_t a;
    asm("{ .reg .u64 t; cvta.to.shared.u64 t, %1; cvt.u32.u64 %0, t; }"
        : "=r"(a) : "l"(p));
    return a;
}
__device__ __forceinline__ void ldsm_x4(uint32_t* r, uint32_t addr) {
    asm volatile("ldmatrix.sync.aligned.m8n8.x4.shared.b16 {%0,%1,%2,%3}, [%4];"
                 : "=r"(r[0]), "=r"(r[1]), "=r"(r[2]), "=r"(r[3]) : "r"(addr));
}
__device__ __forceinline__ void mma16816(float* d, const uint32_t* a,
                                         uint32_t b0, uint32_t b1) {
    asm volatile(
        "mma.sync.aligned.m16n8k16.row.col.f32.bf16.bf16.f32 "
        "{%0,%1,%2,%3}, {%4,%5,%6,%7}, {%8,%9}, {%0,%1,%2,%3};"
        : "+f"(d[0]), "+f"(d[1]), "+f"(d[2]), "+f"(d[3])
        : "r"(a[0]), "r"(a[1]), "r"(a[2]), "r"(a[3]), "r"(b0), "r"(b1));
}
__device__ __forceinline__ void cp16(uint32_t s, const void* g) {
    asm volatile("cp.async.cg.shared.global [%0], [%1], 16;" :: "r"(s), "l"(g));
}
#define CP_COMMIT() asm volatile("cp.async.commit_group;" ::: "memory")
#define CP_WAIT2()  asm volatile("cp.async.wait_group 2;" ::: "memory")
#define CP_WAIT1()  asm volatile("cp.async.wait_group 1;" ::: "memory")
#define CP_WAIT0()  asm volatile("cp.async.wait_group 0;" ::: "memory")

// hi/lo split of 4 floats -> packed bf16x4 (uint2 each); optional exp first
__device__ __forceinline__ void split4(const float4& v, uint2& hi, uint2& lo) {
    float e[4] = {v.x, v.y, v.z, v.w};
    __nv_bfloat16 h[4], l[4];
    #pragma unroll
    for (int j = 0; j < 4; ++j) {
        h[j] = __float2bfloat16(e[j]);
        l[j] = __float2bfloat16(e[j] - __bfloat162float(h[j]));
    }
    __nv_bfloat162 h0 = __halves2bfloat162(h[0], h[1]);
    __nv_bfloat162 h1 = __halves2bfloat162(h[2], h[3]);
    __nv_bfloat162 l0 = __halves2bfloat162(l[0], l[1]);
    __nv_bfloat162 l1 = __halves2bfloat162(l[2], l[3]);
    hi.x = *(uint32_t*)&h0; hi.y = *(uint32_t*)&h1;
    lo.x = *(uint32_t*)&l0; lo.y = *(uint32_t*)&l1;
}
__device__ __forceinline__ void exp_split4(const float4& v, uint2& hi, uint2& lo) {
    float4 e = make_float4(__expf(v.x), __expf(v.y), __expf(v.z), __expf(v.w));
    split4(e, hi, lo);
}

// Full grid barrier: monotonic-counter generation scheme — replay-safe.
__device__ __forceinline__ void grid_barrier() {
    __syncthreads();
    if (threadIdx.x == 0) {
        __threadfence();
        unsigned v = atomicAdd(&g_barctr, 1);
        unsigned target = v - (v % NCTA) + NCTA;
        while ((int)(*(volatile unsigned*)&g_barctr - target) < 0)
            __nanosleep(64);
    }
    __syncthreads();
}

// Per-b barrier: only the 4 CTAs sharing batch b (h = 0..3). Monotonic.
__device__ __forceinline__ void b_barrier(int b) {
    __syncthreads();
    if (threadIdx.x == 0) {
        __threadfence();
        unsigned v = atomicAdd(&g_bctr[b], 1);
        unsigned target = v - (v % NH) + NH;
        while ((int)(*(volatile unsigned*)&g_bctr[b] - target) < 0)
            __nanosleep(32);
        __threadfence();
    }
    __syncthreads();
}

// ---------------------------------------------------------------------------
// smem layout
// ---------------------------------------------------------------------------
#define LDTA 264                           // wide (K=256) tile row stride
#define A_ARR (64 * LDTA * 2)              // 33792 B
#define LDT 72                             // 64-col tile row stride
#define B_ARR (64 * LDT * 2)               // 9216 B
#define OFF_A0 0
#define OFF_A1 A_ARR
#define OFF_B  (2 * A_ARR)                 // 67584 ; 4 stages x (hi,lo)
#define OFF_P  (OFF_B + 8 * B_ARR)         // 141312 ; P fp32 [64][68]
#define OFF_INV (OFF_P + 64 * 68 * 4)      // 158720 ; inv[64]
#define OFF_BIAS (OFF_INV + 256)           // 158976 ; exp(bq),exp(bk),bv [192]
#define FUSED_SMEM (OFF_BIAS + 768)        // 159744
// phase-1 tail reuse: Vt hi/lo = OFF_B +0,+B_ARR ; P hi/lo = +2*B_ARR,+3*B_ARR
// phase-2: C (Wo) preloaded into OFF_A0/OFF_A1 (LDTA layout);
//          EO streams through OFF_B stages 0/1 (2 arrays x 9216 each)

// ---------------------------------------------------------------------------
// ONE persistent kernel, 256 threads (8 warps, 2m x 4n, warp tile 32x16).
// CTA = (h, b), grid (4, 32) = 128 CTAs (all co-resident, 1/SM).
// ---------------------------------------------------------------------------
__global__ void __launch_bounds__(256) k_fused(
    const float* __restrict__ x,
    const float* __restrict__ Wq, const float* __restrict__ Wk,
    const float* __restrict__ Wv, const float* __restrict__ Wo,
    const float* __restrict__ bq, const float* __restrict__ bk,
    const float* __restrict__ bv, const float* __restrict__ bo,
    float* __restrict__ out)
{
    extern __shared__ char smem[];
    const uint32_t sbase = smem_u32(smem);

    const int tid  = threadIdx.x;
    const int lane = tid & 31;
    const int warp = tid >> 5;
    const int wm   = (warp & 1) * 32;
    const int wn   = (warp >> 1) * 16;
    const int h = blockIdx.x;
    const int b = blockIdx.y;
    const int bid = b * NH + h;

    // ======================= PHASE 0: weight conversion ====================
    #pragma unroll
    for (int i = 0; i < 2; ++i) {
        int q = bid * 512 + i * 256 + tid;
        uint2 h2, l2;
        if (q < (NQKV * EDIM) / 4) {
            int idx = q * 4;
            int n = idx / EDIM, k = idx - n * EDIM;
            const float* W = (n < 256) ? Wq : ((n < 512) ? Wk : Wv);
            exp_split4(*(const float4*)&W[(n & 255) * EDIM + k], h2, l2);
            *(uint2*)&g_Bhi[idx] = h2;
            *(uint2*)&g_Blo[idx] = l2;
        } else {
            int idx = q * 4 - NQKV * EDIM;
            exp_split4(*(const float4*)&Wo[idx], h2, l2);
            *(uint2*)&g_Chi[idx] = h2;
            *(uint2*)&g_Clo[idx] = l2;
        }
    }
    grid_barrier();

    // ======================= PHASE 1: qkv GEMM + attention =================
    {
        float* P    = (float*)(smem + OFF_P);     // [64][68] fp32
        float* inv  = (float*)(smem + OFF_INV);
        float* sBias = (float*)(smem + OFF_BIAS); // exp(bq) | exp(bk) | bv
        const int m0 = b * 64;

        auto prefB = [&](int it) {
            const int reg = it >> 2, kc = it & 3;
            const int brow0 = reg * 256 + h * 64;
            const uint32_t s0 = sbase + OFF_B + (uint32_t)(it & 3) * (2 * B_ARR);
            #pragma unroll
            for (int i = 0; i < 2; ++i) {
                int c = tid + 256 * i;
                int r = c >> 3, k8 = (c & 7) * 8;
                uint32_t so = (r * LDT + k8) * 2;
                cp16(s0 + so,         &g_Bhi[(brow0 + r) * EDIM + kc * 64 + k8]);
                cp16(s0 + B_ARR + so, &g_Blo[(brow0 + r) * EDIM + kc * 64 + k8]);
            }
            CP_COMMIT();
        };
        prefB(0); prefB(1); prefB(2);

        // bias preload
        if (tid < 192) {
            int reg = tid >> 6, d = tid & 63;
            float v = (reg == 0) ? __expf(bq[h * 64 + d])
                    : (reg == 1) ? __expf(bk[h * 64 + d])
                                 : bv[h * 64 + d];
            sBias[tid] = v;
        }

        // prolog: LDG x fp32, exp+split, STS into A hi/lo tiles
        #pragma unroll
        for (int i = 0; i < 8; ++i) {
            int c = tid + 256 * i;
            int r = c >> 5, k8 = (c & 31) * 8;
            const float4* xs = (const float4*)&x[(m0 + r) * EDIM + k8];
            float4 v0 = xs[0], v1 = xs[1];
            uint2 h0, l0, h1, l1;
            exp_split4(v0, h0, l0);
            exp_split4(v1, h1, l1);
            uint32_t so = (r * LDTA + k8) * 2;
            *(uint4*)(smem + OFF_A0 + so) = make_uint4(h0.x, h0.y, h1.x, h1.y);
            *(uint4*)(smem + OFF_A1 + so) = make_uint4(l0.x, l0.y, l1.x, l1.y);
        }

        uint32_t aOff[2];
        #pragma unroll
        for (int mf = 0; mf < 2; ++mf)
            aOff[mf] = (uint32_t)(((wm + mf * 16 + (lane & 15)) * LDTA + (lane >> 4) * 8) * 2);
        const uint32_t bOff = (uint32_t)(((wn + (lane >> 4) * 8 + (lane & 7)) * LDT
                                          + ((lane >> 3) & 1) * 8) * 2);

        float acc[2][2][4];
        #pragma unroll
        for (int mf = 0; mf < 2; ++mf)
            #pragma unroll
            for (int nf = 0; nf < 2; ++nf)
                #pragma unroll
                for (int j = 0; j < 4; ++j) acc[mf][nf][j] = 0.f;

        __nv_bfloat16* sVh = (__nv_bfloat16*)(smem + OFF_B);
        __nv_bfloat16* sVl = (__nv_bfloat16*)(smem + OFF_B + B_ARR);

        for (int it = 0; it < 12; ++it) {
            if (it <= 9)       CP_WAIT2();
            else if (it == 10) CP_WAIT1();
            else               CP_WAIT0();
            __syncthreads();            // chunk it visible; stage (it+3)&3 free
            if (it < 9) prefB(it + 3);

            const int kc = it & 3;
            const uint32_t sB = sbase + OFF_B + (uint32_t)(it & 3) * (2 * B_ARR);
            #pragma unroll
            for (int ks = 0; ks < 4; ++ks) {
                const uint32_t aByte = (uint32_t)((kc * 64 + ks * 16) * 2);
                const uint32_t kByte = ks * 32;
                uint32_t ah[2][4], al[2][4], bh[4], bl[4];
                #pragma unroll
                for (int mf = 0; mf < 2; ++mf) {
                    ldsm_x4(ah[mf], sbase + OFF_A0 + aOff[mf] + aByte);
                    ldsm_x4(al[mf], sbase + OFF_A1 + aOff[mf] + aByte);
                }
                ldsm_x4(bh, sB + bOff + kByte);
                ldsm_x4(bl, sB + B_ARR + bOff + kByte);
                #pragma unroll
                for (int mf = 0; mf < 2; ++mf) {
                    #pragma unroll
                    for (int nf = 0; nf < 2; ++nf) {
                        mma16816(acc[mf][nf], ah[mf], bh[nf * 2], bh[nf * 2 + 1]);
                        mma16816(acc[mf][nf], ah[mf], bl[nf * 2], bl[nf * 2 + 1]);
                        mma16816(acc[mf][nf], al[mf], bh[nf * 2], bh[nf * 2 + 1]);
                    }
                }
            }

            if (kc == 3) {
                const int reg = it >> 2;
                #pragma unroll
                for (int mf = 0; mf < 2; ++mf)
                    #pragma unroll
                    for (int nf = 0; nf < 2; ++nf)
                        #pragma unroll
                        for (int j = 0; j < 4; ++j) {
                            int s = wm + mf * 16 + (lane >> 2) + (j >> 1) * 8;
                            int d = wn + nf * 8 + (lane & 3) * 2 + (j & 1);
                            float v = acc[mf][nf][j];
                            if (reg == 0) {
                                P[s * 68 + d] = v * sBias[d];
                            } else if (reg == 1) {
                                P[s * 68 + d] *= v * sBias[64 + d];
                            } else {
                                float vv = __logf(v) + sBias[128 + d];
                                __nv_bfloat16 hb = __float2bfloat16(vv);
                                sVh[d * LDT + s] = hb;
                                sVl[d * LDT + s] = __float2bfloat16(vv - __bfloat162float(hb));
                            }
                            acc[mf][nf][j] = 0.f;
                        }
            }
        }
        __syncthreads();   // P fp32 + Vt bf16 complete; A tiles now DEAD

        // ---- overlap: preload FULL Wo tile (C) into dead A region ---------
        // 64 rows x 256 K, hi+lo, LDTA layout. One cp group; completes in the
        // shadow of the attention tail + b_barrier.
        #pragma unroll
        for (int i = 0; i < 8; ++i) {
            int c = tid + 256 * i;
            int r = c >> 5, k8 = (c & 31) * 8;
            uint32_t so = (r * LDTA + k8) * 2;
            cp16(sbase + OFF_A0 + so, &g_Chi[(h * 64 + r) * EDIM + k8]);
            cp16(sbase + OFF_A1 + so, &g_Clo[(h * 64 + r) * EDIM + k8]);
        }
        CP_COMMIT();

        // ---- parallel rowsum -> inv (4 threads/row + shfl combine) --------
        {
            int r = tid >> 2, seg = tid & 3;
            const float* pr = &P[r * 68 + seg * 16];
            float s = 0.f;
            #pragma unroll
            for (int g = 0; g < 4; ++g) {
                float4 p4 = *(const float4*)&pr[g * 4];
                s += p4.x + p4.y + p4.z + p4.w;
            }
            s += __shfl_xor_sync(0xffffffffu, s, 1);
            s += __shfl_xor_sync(0xffffffffu, s, 2);
            if (seg == 0) inv[r] = 1.0f / s;
        }
        __syncthreads();

        // ---- attn = P * inv -> bf16 hi/lo split tiles ---------------------
        {
            __nv_bfloat16* sPh = (__nv_bfloat16*)(smem + OFF_B + 2 * B_ARR);
            __nv_bfloat16* sPl = (__nv_bfloat16*)(smem + OFF_B + 3 * B_ARR);
            int r = tid >> 2, c0 = (tid & 3) * 16;
            float iv = inv[r];
            #pragma unroll
            for (int g = 0; g < 4; ++g) {
                float4 p4 = *(const float4*)&P[r * 68 + c0 + g * 4];
                p4.x *= iv; p4.y *= iv; p4.z *= iv; p4.w *= iv;
                uint2 h2, l2; split4(p4, h2, l2);
                *(uint2*)&sPh[r * LDT + c0 + g * 4] = h2;
                *(uint2*)&sPl[r * LDT + c0 + g * 4] = l2;
            }
        }
        __syncthreads();

        // ---- out = attn @ V on tensor pipe; EO = exp(out) -----------------
        {
            const uint32_t PHB = sbase + OFF_B + 2 * B_ARR;
            const uint32_t PLB = sbase + OFF_B + 3 * B_ARR;
            const uint32_t VHB = sbase + OFF_B;
            const uint32_t VLB = sbase + OFF_B + B_ARR;
            uint32_t aO[2];
            #pragma unroll
            for (int mf = 0; mf < 2; ++mf)
                aO[mf] = (uint32_t)(((wm + mf * 16 + (lane & 15)) * LDT + (lane >> 4) * 8) * 2);

            #pragma unroll
            for (int ks = 0; ks < 4; ++ks) {
                const uint32_t kByte = ks * 32;
                uint32_t ah[2][4], al[2][4], bh[4], bl[4];
                #pragma unroll
                for (int mf = 0; mf < 2; ++mf) {
                    ldsm_x4(ah[mf], PHB + aO[mf] + kByte);
                    ldsm_x4(al[mf], PLB + aO[mf] + kByte);
                }
                ldsm_x4(bh, VHB + bOff + kByte);
                ldsm_x4(bl, VLB + bOff + kByte);
                #pragma unroll
                for (int mf = 0; mf < 2; ++mf) {
                    #pragma unroll
                    for (int nf = 0; nf < 2; ++nf) {
                        mma16816(acc[mf][nf], ah[mf], bh[nf * 2], bh[nf * 2 + 1]);
                        mma16816(acc[mf][nf], ah[mf], bl[nf * 2], bl[nf * 2 + 1]);
                        mma16816(acc[mf][nf], al[mf], bh[nf * 2], bh[nf * 2 + 1]);
                    }
                }
            }

            // epilogue: EO = exp(out), packed bf16x2 global stores
            #pragma unroll
            for (int mf = 0; mf < 2; ++mf)
                #pragma unroll
                for (int nf = 0; nf < 2; ++nf)
                    #pragma unroll
                    for (int jp = 0; jp < 2; ++jp) {
                        int s = wm + mf * 16 + (lane >> 2) + jp * 8;
                        int e = wn + nf * 8 + (lane & 3) * 2;
                        float eo0 = __expf(acc[mf][nf][jp * 2 + 0]);
                        float eo1 = __expf(acc[mf][nf][jp * 2 + 1]);
                        __nv_bfloat16 h0 = __float2bfloat16(eo0);
                        __nv_bfloat16 h1 = __float2bfloat16(eo1);
                        __nv_bfloat162 hh = __halves2bfloat162(h0, h1);
                        __nv_bfloat162 ll = __halves2bfloat162(
                            __float2bfloat16(eo0 - __bfloat162float(h0)),
                            __float2bfloat16(eo1 - __bfloat162float(h1)));
                        int gi = (b * 64 + s) * EDIM + h * 64 + e;
                        *(uint32_t*)&g_EOhi[gi] = *(uint32_t*)&hh;
                        *(uint32_t*)&g_EOlo[gi] = *(uint32_t*)&ll;
                    }
        }
    }
    b_barrier(b);   // only the 4 CTAs sharing batch b need each other's EO

    // ======================= PHASE 2: output projection ====================
    // C (Wo) already resident in OFF_A0/OFF_A1 (group committed pre-tail).
    // Loop streams only EO through OFF_B stages 0/1.
    {
        const int m0 = b * 64;         // row tile
        const int n0 = h * 64;         // col tile — C rows (already loaded)
        (void)n0;

        uint32_t aOff[2];
        #pragma unroll
        for (int mf = 0; mf < 2; ++mf)
            aOff[mf] = (uint32_t)(((wm + mf * 16 + (lane & 15)) * LDT + (lane >> 4) * 8) * 2);
        // C-side ldmatrix offsets in the wide LDTA layout
        const uint32_t bOffC = (uint32_t)(((wn + (lane >> 4) * 8 + (lane & 7)) * LDTA
                                           + ((lane >> 3) & 1) * 8) * 2);

        float acc[2][2][4];
        #pragma unroll
        for (int mf = 0; mf < 2; ++mf)
            #pragma unroll
            for (int nf = 0; nf < 2; ++nf)
                #pragma unroll
                for (int j = 0; j < 4; ++j) acc[mf][nf][j] = 0.f;

        auto prefetchEO = [&](int kc, int stg) {
            const int kb = kc * 64;
            const uint32_t s0 = sbase + OFF_B + (uint32_t)stg * (2 * B_ARR);
            #pragma unroll
            for (int i = 0; i < 2; ++i) {
                int c = tid + 256 * i;
                int r = c >> 3, k8 = (c & 7) * 8;
                uint32_t so = (r * LDT + k8) * 2;
                cp16(s0 + so,         &g_EOhi[(m0 + r) * EDIM + kb + k8]);
                cp16(s0 + B_ARR + so, &g_EOlo[(m0 + r) * EDIM + kb + k8]);
            }
            CP_COMMIT();
        };

        prefetchEO(0, 0);

        for (int kc = 0; kc < 4; ++kc) {
            if (kc < 3) prefetchEO(kc + 1, (kc + 1) & 1);
            if (kc < 3) CP_WAIT1(); else CP_WAIT0();   // drains C group first
            __syncthreads();

            const uint32_t sE = sbase + OFF_B + (uint32_t)(kc & 1) * (2 * B_ARR);
            #pragma unroll
            for (int ks = 0; ks < 4; ++ks) {
                const uint32_t kByte = ks * 32;
                const uint32_t cByte = (uint32_t)((kc * 64 + ks * 16) * 2);
                uint32_t ah[2][4], al[2][4], bh[4], bl[4];
                #pragma unroll
                for (int mf = 0; mf < 2; ++mf) {
                    ldsm_x4(ah[mf], sE + aOff[mf] + kByte);
                    ldsm_x4(al[mf], sE + B_ARR + aOff[mf] + kByte);
                }
                ldsm_x4(bh, sbase + OFF_A0 + bOffC + cByte);
                ldsm_x4(bl, sbase + OFF_A1 + bOffC + cByte);
                #pragma unroll
                for (int mf = 0; mf < 2; ++mf) {
                    #pragma unroll
                    for (int nf = 0; nf < 2; ++nf) {
                        mma16816(acc[mf][nf], ah[mf], bh[nf * 2], bh[nf * 2 + 1]);
                        mma16816(acc[mf][nf], ah[mf], bl[nf * 2], bl[nf * 2 + 1]);
                        mma16816(acc[mf][nf], al[mf], bh[nf * 2], bh[nf * 2 + 1]);
                    }
                }
            }
            __syncthreads();
        }

        const int l4 = lane >> 2;
        const int l2 = (lane & 3) * 2;
        #pragma unroll
        for (int mf = 0; mf < 2; ++mf) {
            #pragma unroll
            for (int nf = 0; nf < 2; ++nf) {
                int gr = m0 + wm + mf * 16 + l4;
                int gc = h * 64 + wn + nf * 8 + l2;
                float r[4];
                #pragma unroll
                for (int j = 0; j < 4; ++j)
                    r[j] = __logf(acc[mf][nf][j]) + bo[gc + (j & 1)];
                *(float2*)&out[gr * EDIM + gc]       = make_float2(r[0], r[1]);
                *(float2*)&out[(gr + 8) * EDIM + gc] = make_float2(r[2], r[3]);
            }
        }
    }
}

// ---------------------------------------------------------------------------
extern "C" void kernel_launch(void* const* d_in, const int* in_sizes, int n_in,
                              void* d_out, int out_size)
{
    const float* x  = (const float*)d_in[0];
    const float* Wq = (const float*)d_in[1];
    const float* bq = (const float*)d_in[2];
    const float* Wk = (const float*)d_in[3];
    const float* bk = (const float*)d_in[4];
    const float* Wv = (const float*)d_in[5];
    const float* bv = (const float*)d_in[6];
    const float* Wo = (const float*)d_in[7];
    const float* bo = (const float*)d_in[8];
    float* out = (float*)d_out;

    static bool init = false;
    if (!init) {
        cudaFuncSetAttribute(k_fused, cudaFuncAttributeMaxDynamicSharedMemorySize, FUSED_SMEM);
        init = true;
    }

    dim3 grid(NH, 32);   // 128 CTAs — all co-resident (1/SM, 148 SMs)
    k_fused<<<grid, 256, FUSED_SMEM>>>(x, Wq, Wk, Wv, Wo, bq, bk, bv, bo, out);
}